// round 1
// baseline (speedup 1.0000x reference)
#include <cuda_runtime.h>
#include <cuda_bf16.h>
#include <math.h>

// ---------------- problem constants ----------------
#define BB   2
#define SS   2048
#define TT   4096          // B*S
#define HID  2048
#define HH   16
#define DN   128
#define DR   64
#define DV   128
#define LL   512
#define DQ   (DN + DR)     // 192
#define DK   (LL + DR)     // 576

// ---------------- scratch (static device memory; no allocations) ----------------
__device__ float g_q     [(long)TT * HH * DQ];        // 50 MB   q projection
__device__ float g_ckv   [(long)TT * DK];             // 9.4 MB  raw kv_a proj
__device__ float g_kfull [(long)TT * DK];             // 9.4 MB  [rmsnorm kv_c | roped k_rot]
__device__ float g_qfull [(long)TT * HH * DK];        // 151 MB  [q_lat | roped q_rot]
__device__ float g_scores[(long)BB * HH * SS * SS];   // 512 MB  scores -> probs in place
__device__ float g_outlat[(long)TT * HH * LL];        // 134 MB  attn @ kv_c
__device__ float g_y     [(long)TT * HH * DV];        // 33 MB   per-head out @ W_UV

// ---------------- generic SGEMM ----------------
// C[M,N] = alpha * A @ op(B)
//   BT=true : B is [N,K] row-major (C = A @ B^T)
//   BT=false: B is [K,N] row-major (C = A @ B)
// CAUSAL=1 : skip blocks strictly above the diagonal (scores; masked entries never read)
// CAUSAL=2 : clamp K loop to row0+BM (attn rows are zero beyond the diagonal)
// Batched over grid.z: z = b*nH + h, per-matrix offsets (elems) aB/aH etc.
// Requirements (all satisfied by the call sites): M % 128 == 0, K % 8 == 0,
// all strides and base offsets multiples of 4 floats (16B-aligned float4 loads).
constexpr int BMt = 128, BNt = 128, BKt = 8, TMt = 8, TNt = 8;

template<bool BT, int CAUSAL>
__global__ __launch_bounds__(256)
void sgemm_kernel(const float* __restrict__ A, const float* __restrict__ Bm,
                  float* __restrict__ C,
                  int M, int N, int K, int lda, int ldb, int ldc, float alpha,
                  long aB, long aH, long bB, long bH, long cB, long cH, int nH)
{
    int z  = blockIdx.z;
    int bb = z / nH, hh = z - bb * nH;
    A  += (long)bb * aB + (long)hh * aH;
    Bm += (long)bb * bB + (long)hh * bH;
    C  += (long)bb * cB + (long)hh * cH;

    const int row0 = blockIdx.y * BMt;
    const int col0 = blockIdx.x * BNt;
    if (CAUSAL == 1 && col0 > row0 + BMt - 1) return;
    int Keff = K;
    if (CAUSAL == 2) { int lim = row0 + BMt; Keff = lim < K ? lim : K; }

    __shared__ float As[BKt][BMt + 4];
    __shared__ float Bs[BKt][BNt + 4];

    const int tid = threadIdx.x;          // 256 threads
    const int tx  = tid & 15;             // 16
    const int ty  = tid >> 4;             // 16

    float acc[TMt][TNt];
    #pragma unroll
    for (int i = 0; i < TMt; i++)
        #pragma unroll
        for (int j = 0; j < TNt; j++) acc[i][j] = 0.f;

    // A tile: 128 rows x 8 k, one float4 per thread
    const int arow = tid >> 1;
    const int acol = (tid & 1) << 2;
    // NN B tile: 8 k x 128 cols, one float4 per thread
    const int nbk = tid >> 5;
    const int nbc = (tid & 31) << 2;

    for (int k0 = 0; k0 < Keff; k0 += BKt) {
        float4 av = *reinterpret_cast<const float4*>(A + (long)(row0 + arow) * lda + k0 + acol);
        As[acol + 0][arow] = av.x; As[acol + 1][arow] = av.y;
        As[acol + 2][arow] = av.z; As[acol + 3][arow] = av.w;

        if (BT) {
            int bc = col0 + arow;                 // output column = B row
            float4 bv = make_float4(0.f, 0.f, 0.f, 0.f);
            if (bc < N)
                bv = *reinterpret_cast<const float4*>(Bm + (long)bc * ldb + k0 + acol);
            Bs[acol + 0][arow] = bv.x; Bs[acol + 1][arow] = bv.y;
            Bs[acol + 2][arow] = bv.z; Bs[acol + 3][arow] = bv.w;
        } else {
            int bc = col0 + nbc;
            float4 bv = make_float4(0.f, 0.f, 0.f, 0.f);
            if (bc < N)
                bv = *reinterpret_cast<const float4*>(Bm + (long)(k0 + nbk) * ldb + bc);
            *reinterpret_cast<float4*>(&Bs[nbk][nbc]) = bv;
        }
        __syncthreads();

        #pragma unroll
        for (int kk = 0; kk < BKt; kk++) {
            float ar[TMt], br[TNt];
            #pragma unroll
            for (int i = 0; i < TMt; i++) ar[i] = As[kk][ty * TMt + i];
            #pragma unroll
            for (int j = 0; j < TNt; j++) br[j] = Bs[kk][tx * TNt + j];
            #pragma unroll
            for (int i = 0; i < TMt; i++)
                #pragma unroll
                for (int j = 0; j < TNt; j++)
                    acc[i][j] = fmaf(ar[i], br[j], acc[i][j]);
        }
        __syncthreads();
    }

    #pragma unroll
    for (int i = 0; i < TMt; i++) {
        int r = row0 + ty * TMt + i;
        #pragma unroll
        for (int j = 0; j < TNt; j++) {
            int c = col0 + tx * TNt + j;
            if (c < N) C[(long)r * ldc + c] = alpha * acc[i][j];
        }
    }
}

// ---------------- kv: RMSNorm + RoPE(k) -> k_full [T,576] ----------------
__global__ __launch_bounds__(256)
void kv_transform_kernel(const float* __restrict__ ckv,
                         const float* __restrict__ cs, const float* __restrict__ sn,
                         const float* __restrict__ lnw, float* __restrict__ kfull)
{
    const int t = blockIdx.x;
    const float* row = ckv + (long)t * DK;
    const int tid = threadIdx.x;

    float x0 = row[tid], x1 = row[tid + 256];
    float ss = x0 * x0 + x1 * x1;
    #pragma unroll
    for (int o = 16; o; o >>= 1) ss += __shfl_xor_sync(0xffffffffu, ss, o);
    __shared__ float red[8];
    if ((tid & 31) == 0) red[tid >> 5] = ss;
    __syncthreads();
    float tot = 0.f;
    #pragma unroll
    for (int w = 0; w < 8; w++) tot += red[w];
    float inv = rsqrtf(tot / (float)LL + 1e-6f);

    float* out = kfull + (long)t * DK;
    out[tid]       = x0 * inv * lnw[tid];
    out[tid + 256] = x1 * inv * lnw[tid + 256];

    if (tid < DR) {
        int j = tid;
        float c = cs[(long)t * DR + j], s = sn[(long)t * DR + j];
        const float* r = row + LL;
        float val;
        if (j < 32) val = r[2 * j] * c - r[2 * j + 1] * s;
        else { int m = j - 32; val = r[2 * m + 1] * c + r[2 * m] * s; }
        out[LL + j] = val;
    }
}

// ---------------- q RoPE -> q_full[..., 512:576] ----------------
__global__ __launch_bounds__(256)
void q_rope_kernel(const float* __restrict__ q,
                   const float* __restrict__ cs, const float* __restrict__ sn,
                   float* __restrict__ qfull)
{
    const int t = blockIdx.x;
    const int tid = threadIdx.x;
    #pragma unroll
    for (int l = 0; l < 4; l++) {
        int idx = tid + l * 256;          // 0..1023 = h*64 + j
        int h = idx >> 6, j = idx & 63;
        const float* r = q + ((long)t * HH + h) * DQ + DN;
        float c = cs[(long)t * DR + j], s = sn[(long)t * DR + j];
        float val;
        if (j < 32) val = r[2 * j] * c - r[2 * j + 1] * s;
        else { int m = j - 32; val = r[2 * m + 1] * c + r[2 * m] * s; }
        qfull[((long)t * HH + h) * DK + LL + j] = val;
    }
}

// ---------------- causal softmax (in place), zero-fills t > s ----------------
__global__ __launch_bounds__(256)
void softmax_kernel(float* __restrict__ P)
{
    const int s = blockIdx.x;
    long base = ((long)blockIdx.y * SS + s) * (long)SS;
    const int valid = s + 1;
    const int tid = threadIdx.x;

    float v[8];
    float mx = -1e30f;
    #pragma unroll
    for (int l = 0; l < 8; l++) {
        int idx = tid + l * 256;
        v[l] = (idx < valid) ? P[base + idx] : -1e30f;
        mx = fmaxf(mx, v[l]);
    }
    __shared__ float red[8];
    #pragma unroll
    for (int o = 16; o; o >>= 1) mx = fmaxf(mx, __shfl_xor_sync(0xffffffffu, mx, o));
    if ((tid & 31) == 0) red[tid >> 5] = mx;
    __syncthreads();
    float m = red[0];
    #pragma unroll
    for (int w = 1; w < 8; w++) m = fmaxf(m, red[w]);
    __syncthreads();

    float sum = 0.f;
    #pragma unroll
    for (int l = 0; l < 8; l++) {
        int idx = tid + l * 256;
        v[l] = (idx < valid) ? __expf(v[l] - m) : 0.f;
        sum += v[l];
    }
    #pragma unroll
    for (int o = 16; o; o >>= 1) sum += __shfl_xor_sync(0xffffffffu, sum, o);
    if ((tid & 31) == 0) red[tid >> 5] = sum;
    __syncthreads();
    float tot = 0.f;
    #pragma unroll
    for (int w = 0; w < 8; w++) tot += red[w];
    float invs = 1.f / tot;

    #pragma unroll
    for (int l = 0; l < 8; l++) {
        int idx = tid + l * 256;
        P[base + idx] = v[l] * invs;
    }
}

// ---------------- launch ----------------
extern "C" void kernel_launch(void* const* d_in, const int* in_sizes, int n_in,
                              void* d_out, int out_size)
{
    const float* x    = (const float*)d_in[0];   // hidden_states [2,2048,2048]
    const float* cs   = (const float*)d_in[1];   // cos [4096,64]
    const float* sn   = (const float*)d_in[2];   // sin [4096,64]
    const float* qw   = (const float*)d_in[3];   // q_proj_w   [3072,2048]
    const float* kvw  = (const float*)d_in[4];   // kv_a_proj_w[576,2048]
    const float* lnw  = (const float*)d_in[5];   // kv_a_ln_w  [512]
    const float* wukt = (const float*)d_in[6];   // W_UK_T [16,128,512]
    const float* wuv  = (const float*)d_in[7];   // W_UV   [16,512,128]
    const float* ow   = (const float*)d_in[8];   // o_proj_w [2048,2048]
    float* out        = (float*)d_out;           // [4096,2048]

    float *pq, *pckv, *pkf, *pqf, *psc, *pol, *py;
    cudaGetSymbolAddress((void**)&pq,   g_q);
    cudaGetSymbolAddress((void**)&pckv, g_ckv);
    cudaGetSymbolAddress((void**)&pkf,  g_kfull);
    cudaGetSymbolAddress((void**)&pqf,  g_qfull);
    cudaGetSymbolAddress((void**)&psc,  g_scores);
    cudaGetSymbolAddress((void**)&pol,  g_outlat);
    cudaGetSymbolAddress((void**)&py,   g_y);

    const float scale = 1.0f / sqrtf((float)(DN + DR));

    // 1) q = x @ q_proj_w^T         [4096,3072]
    sgemm_kernel<true, 0><<<dim3(24, 32, 1), 256>>>(
        x, qw, pq, TT, HH * DQ, HID, HID, HID, HH * DQ, 1.f,
        0, 0, 0, 0, 0, 0, 1);

    // 2) ckv = x @ kv_a_proj_w^T    [4096,576]
    sgemm_kernel<true, 0><<<dim3(5, 32, 1), 256>>>(
        x, kvw, pckv, TT, DK, HID, HID, HID, DK, 1.f,
        0, 0, 0, 0, 0, 0, 1);

    // 3) k_full = [rmsnorm(kv_c)*w | rope(k_rot)]
    kv_transform_kernel<<<TT, 256>>>(pckv, cs, sn, lnw, pkf);

    // 4) q_full[...,512:576] = rope(q_rot)
    q_rope_kernel<<<TT, 256>>>(pq, cs, sn, pqf);

    // 5) q_full[...,0:512] = q_pass @ W_UK_T[h]   (batched over h)
    sgemm_kernel<false, 0><<<dim3(4, 32, HH), 256>>>(
        pq, wukt, pqf, TT, LL, DN, HH * DQ, LL, HH * DK, 1.f,
        0, DQ, 0, (long)DN * LL, 0, DK, HH);

    // 6) scores = scale * q_full @ k_full^T   (batched over b,h; upper blocks skipped)
    sgemm_kernel<true, 1><<<dim3(16, 16, BB * HH), 256>>>(
        pqf, pkf, psc, SS, SS, DK, HH * DK, DK, SS, scale,
        (long)SS * HH * DK, DK,
        (long)SS * DK, 0,
        (long)HH * SS * SS, (long)SS * SS, HH);

    // 7) causal softmax in place
    softmax_kernel<<<dim3(SS, BB * HH), 256>>>(psc);

    // 8) out_lat = attn @ kv_c   (K loop clamped by causality)
    sgemm_kernel<false, 2><<<dim3(4, 16, BB * HH), 256>>>(
        psc, pkf, pol, SS, LL, SS, SS, DK, HH * LL, 1.f,
        (long)HH * SS * SS, (long)SS * SS,
        (long)SS * DK, 0,
        (long)SS * HH * LL, LL, HH);

    // 9) y[:, h*128:(h+1)*128] = out_lat[:,h,:] @ W_UV[h]
    sgemm_kernel<false, 0><<<dim3(1, 32, HH), 256>>>(
        pol, wuv, py, TT, DV, LL, HH * LL, DV, HH * DV, 1.f,
        0, LL, 0, (long)LL * DV, 0, DV, HH);

    // 10) out = y @ o_proj_w^T
    sgemm_kernel<true, 0><<<dim3(16, 32, 1), 256>>>(
        py, ow, out, TT, HID, HH * DV, HH * DV, HH * DV, HID, 1.f,
        0, 0, 0, 0, 0, 0, 1);
}

// round 2
// speedup vs baseline: 2.3649x; 2.3649x over previous
#include <cuda_runtime.h>
#include <cuda_bf16.h>
#include <math.h>
#include <stdint.h>

// ---------------- problem constants ----------------
#define BB   2
#define SS   2048
#define TT   4096          // B*S
#define HID  2048
#define HH   16
#define DN   128
#define DR   64
#define DV   128
#define LL   512
#define DQ   (DN + DR)     // 192
#define DK   (LL + DR)     // 576

// ---------------- scratch (static device memory; no allocations) ----------------
__device__ float g_q     [(long)TT * HH * DQ];
__device__ float g_ckv   [(long)TT * DK];
__device__ float g_kfull [(long)TT * DK];
__device__ float g_qfull [(long)TT * HH * DK];
__device__ float g_scores[(long)BB * HH * SS * SS];
__device__ float g_outlat[(long)TT * HH * LL];
__device__ float g_y     [(long)TT * HH * DV];

// ---------------- tf32 helpers ----------------
__device__ __forceinline__ float f2tf(float x) {
    uint32_t u;
    asm("cvt.rna.tf32.f32 %0, %1;" : "=r"(u) : "f"(x));
    return __uint_as_float(u);
}

__device__ __forceinline__ void mma_tf32(float c[4], const float a[4], const float b[2]) {
    asm volatile(
        "mma.sync.aligned.m16n8k8.row.col.f32.tf32.tf32.f32 "
        "{%0,%1,%2,%3}, {%4,%5,%6,%7}, {%8,%9}, {%0,%1,%2,%3};"
        : "+f"(c[0]), "+f"(c[1]), "+f"(c[2]), "+f"(c[3])
        : "r"(__float_as_uint(a[0])), "r"(__float_as_uint(a[1])),
          "r"(__float_as_uint(a[2])), "r"(__float_as_uint(a[3])),
          "r"(__float_as_uint(b[0])), "r"(__float_as_uint(b[1])));
}

// ---------------- tensor-core TF32 GEMM ----------------
// C[M,N] = alpha * A @ op(B)
//   BT=true : B is [N,K] row-major (C = A @ B^T)
//   BT=false: B is [K,N] row-major (C = A @ B)
// CAUSAL=1 : skip blocks strictly above the diagonal (scores)
// CAUSAL=2 : clamp K loop to row0+BM (attn rows zero beyond diagonal)
// Batched over grid.z: z = b*nH + h with per-matrix element offsets.
// Requirements: M % 128 == 0, K % 16 == 0, A/B rows 16B-aligned.
constexpr int BM = 128, BN = 128, BK = 16;
constexpr int SKP = BK + 4;   // smem row stride (floats): 20 -> conflict-free frags

template<bool BT, int CAUSAL>
__global__ __launch_bounds__(256)
void gemm_tc(const float* __restrict__ A, const float* __restrict__ Bm,
             float* __restrict__ C,
             int M, int N, int K, int lda, int ldb, int ldc, float alpha,
             long aB, long aH, long bB, long bH, long cB, long cH, int nH)
{
    int z  = blockIdx.z;
    int bb = z / nH, hh = z - bb * nH;
    A  += (long)bb * aB + (long)hh * aH;
    Bm += (long)bb * bB + (long)hh * bH;
    C  += (long)bb * cB + (long)hh * cH;

    const int row0 = blockIdx.y * BM;
    const int col0 = blockIdx.x * BN;
    if (CAUSAL == 1 && col0 > row0 + BM - 1) return;
    int Keff = K;
    if (CAUSAL == 2) { int lim = row0 + BM; Keff = lim < K ? lim : K; }

    __shared__ float As[BM][SKP];   // [m][k]
    __shared__ float Bs[BN][SKP];   // [n][k]

    const int tid  = threadIdx.x;
    const int lane = tid & 31;
    const int warp = tid >> 5;
    const int wm   = warp & 3;      // 4 warps along M
    const int wn   = warp >> 2;     // 2 warps along N
    const int gid  = lane >> 2;     // 0..7
    const int tig  = lane & 3;      // 0..3

    float acc[2][8][4];
    #pragma unroll
    for (int i = 0; i < 2; i++)
        #pragma unroll
        for (int j = 0; j < 8; j++)
            #pragma unroll
            for (int r = 0; r < 4; r++) acc[i][j][r] = 0.f;

    // global-load assignments
    const int arow = tid >> 1;            // 0..127
    const int acol = (tid & 1) << 3;      // 0 or 8
    const int nbk  = tid >> 4;            // 0..15 (NN: k row)
    const int nbc  = tid & 15;            // NN: col lane

    float4 pa0, pa1, pb0, pb1;            // prefetch regs (BT path)
    float  pbn[8];                        // prefetch regs (NN path)

    auto load_tile = [&](int k0) {
        pa0 = *reinterpret_cast<const float4*>(A + (long)(row0 + arow) * lda + k0 + acol);
        pa1 = *reinterpret_cast<const float4*>(A + (long)(row0 + arow) * lda + k0 + acol + 4);
        if (BT) {
            int bc = col0 + arow;
            if (bc < N) {
                pb0 = *reinterpret_cast<const float4*>(Bm + (long)bc * ldb + k0 + acol);
                pb1 = *reinterpret_cast<const float4*>(Bm + (long)bc * ldb + k0 + acol + 4);
            } else {
                pb0 = make_float4(0.f,0.f,0.f,0.f);
                pb1 = make_float4(0.f,0.f,0.f,0.f);
            }
        } else {
            const float* brow = Bm + (long)(k0 + nbk) * ldb + col0;
            #pragma unroll
            for (int i = 0; i < 8; i++) {
                int c = nbc + 16 * i;
                pbn[i] = (col0 + c < N) ? brow[c] : 0.f;
            }
        }
    };

    auto store_tile = [&]() {
        As[arow][acol + 0] = f2tf(pa0.x); As[arow][acol + 1] = f2tf(pa0.y);
        As[arow][acol + 2] = f2tf(pa0.z); As[arow][acol + 3] = f2tf(pa0.w);
        As[arow][acol + 4] = f2tf(pa1.x); As[arow][acol + 5] = f2tf(pa1.y);
        As[arow][acol + 6] = f2tf(pa1.z); As[arow][acol + 7] = f2tf(pa1.w);
        if (BT) {
            Bs[arow][acol + 0] = f2tf(pb0.x); Bs[arow][acol + 1] = f2tf(pb0.y);
            Bs[arow][acol + 2] = f2tf(pb0.z); Bs[arow][acol + 3] = f2tf(pb0.w);
            Bs[arow][acol + 4] = f2tf(pb1.x); Bs[arow][acol + 5] = f2tf(pb1.y);
            Bs[arow][acol + 6] = f2tf(pb1.z); Bs[arow][acol + 7] = f2tf(pb1.w);
        } else {
            #pragma unroll
            for (int i = 0; i < 8; i++)
                Bs[nbc + 16 * i][nbk] = f2tf(pbn[i]);
        }
    };

    load_tile(0);
    for (int k0 = 0; k0 < Keff; k0 += BK) {
        __syncthreads();
        store_tile();
        __syncthreads();
        if (k0 + BK < Keff) load_tile(k0 + BK);

        #pragma unroll
        for (int kk = 0; kk < BK; kk += 8) {
            float a[2][4];
            #pragma unroll
            for (int mi = 0; mi < 2; mi++) {
                int mr = wm * 32 + mi * 16 + gid;
                a[mi][0] = As[mr    ][kk + tig    ];
                a[mi][1] = As[mr + 8][kk + tig    ];
                a[mi][2] = As[mr    ][kk + tig + 4];
                a[mi][3] = As[mr + 8][kk + tig + 4];
            }
            float b[8][2];
            #pragma unroll
            for (int ni = 0; ni < 8; ni++) {
                int nc = wn * 64 + ni * 8 + gid;
                b[ni][0] = Bs[nc][kk + tig    ];
                b[ni][1] = Bs[nc][kk + tig + 4];
            }
            #pragma unroll
            for (int mi = 0; mi < 2; mi++)
                #pragma unroll
                for (int ni = 0; ni < 8; ni++)
                    mma_tf32(acc[mi][ni], a[mi], b[ni]);
        }
    }

    // epilogue
    #pragma unroll
    for (int mi = 0; mi < 2; mi++) {
        int r0 = row0 + wm * 32 + mi * 16 + gid;
        #pragma unroll
        for (int ni = 0; ni < 8; ni++) {
            int c = col0 + wn * 64 + ni * 8 + 2 * tig;
            if (c < N) {
                float2 v0 = make_float2(alpha * acc[mi][ni][0], alpha * acc[mi][ni][1]);
                float2 v1 = make_float2(alpha * acc[mi][ni][2], alpha * acc[mi][ni][3]);
                *reinterpret_cast<float2*>(C + (long)r0 * ldc + c)       = v0;
                *reinterpret_cast<float2*>(C + (long)(r0 + 8) * ldc + c) = v1;
            }
        }
    }
}

// ---------------- kv: RMSNorm + RoPE(k) -> k_full [T,576] ----------------
__global__ __launch_bounds__(256)
void kv_transform_kernel(const float* __restrict__ ckv,
                         const float* __restrict__ cs, const float* __restrict__ sn,
                         const float* __restrict__ lnw, float* __restrict__ kfull)
{
    const int t = blockIdx.x;
    const float* row = ckv + (long)t * DK;
    const int tid = threadIdx.x;

    float x0 = row[tid], x1 = row[tid + 256];
    float ss = x0 * x0 + x1 * x1;
    #pragma unroll
    for (int o = 16; o; o >>= 1) ss += __shfl_xor_sync(0xffffffffu, ss, o);
    __shared__ float red[8];
    if ((tid & 31) == 0) red[tid >> 5] = ss;
    __syncthreads();
    float tot = 0.f;
    #pragma unroll
    for (int w = 0; w < 8; w++) tot += red[w];
    float inv = rsqrtf(tot / (float)LL + 1e-6f);

    float* out = kfull + (long)t * DK;
    out[tid]       = x0 * inv * lnw[tid];
    out[tid + 256] = x1 * inv * lnw[tid + 256];

    if (tid < DR) {
        int j = tid;
        float c = cs[(long)t * DR + j], s = sn[(long)t * DR + j];
        const float* r = row + LL;
        float val;
        if (j < 32) val = r[2 * j] * c - r[2 * j + 1] * s;
        else { int m = j - 32; val = r[2 * m + 1] * c + r[2 * m] * s; }
        out[LL + j] = val;
    }
}

// ---------------- q RoPE -> q_full[..., 512:576] ----------------
__global__ __launch_bounds__(256)
void q_rope_kernel(const float* __restrict__ q,
                   const float* __restrict__ cs, const float* __restrict__ sn,
                   float* __restrict__ qfull)
{
    const int t = blockIdx.x;
    const int tid = threadIdx.x;
    #pragma unroll
    for (int l = 0; l < 4; l++) {
        int idx = tid + l * 256;          // 0..1023 = h*64 + j
        int h = idx >> 6, j = idx & 63;
        const float* r = q + ((long)t * HH + h) * DQ + DN;
        float c = cs[(long)t * DR + j], s = sn[(long)t * DR + j];
        float val;
        if (j < 32) val = r[2 * j] * c - r[2 * j + 1] * s;
        else { int m = j - 32; val = r[2 * m + 1] * c + r[2 * m] * s; }
        qfull[((long)t * HH + h) * DK + LL + j] = val;
    }
}

// ---------------- causal softmax (in place), zero-fills t > s ----------------
__global__ __launch_bounds__(256)
void softmax_kernel(float* __restrict__ P)
{
    const int s = blockIdx.x;
    long base = ((long)blockIdx.y * SS + s) * (long)SS;
    const int valid = s + 1;
    const int tid = threadIdx.x;

    float v[8];
    float mx = -1e30f;
    #pragma unroll
    for (int l = 0; l < 8; l++) {
        int idx = tid + l * 256;
        v[l] = (idx < valid) ? P[base + idx] : -1e30f;
        mx = fmaxf(mx, v[l]);
    }
    __shared__ float red[8];
    #pragma unroll
    for (int o = 16; o; o >>= 1) mx = fmaxf(mx, __shfl_xor_sync(0xffffffffu, mx, o));
    if ((tid & 31) == 0) red[tid >> 5] = mx;
    __syncthreads();
    float m = red[0];
    #pragma unroll
    for (int w = 1; w < 8; w++) m = fmaxf(m, red[w]);
    __syncthreads();

    float sum = 0.f;
    #pragma unroll
    for (int l = 0; l < 8; l++) {
        int idx = tid + l * 256;
        v[l] = (idx < valid) ? __expf(v[l] - m) : 0.f;
        sum += v[l];
    }
    #pragma unroll
    for (int o = 16; o; o >>= 1) sum += __shfl_xor_sync(0xffffffffu, sum, o);
    if ((tid & 31) == 0) red[tid >> 5] = sum;
    __syncthreads();
    float tot = 0.f;
    #pragma unroll
    for (int w = 0; w < 8; w++) tot += red[w];
    float invs = 1.f / tot;

    #pragma unroll
    for (int l = 0; l < 8; l++) {
        int idx = tid + l * 256;
        P[base + idx] = v[l] * invs;
    }
}

// ---------------- launch ----------------
extern "C" void kernel_launch(void* const* d_in, const int* in_sizes, int n_in,
                              void* d_out, int out_size)
{
    const float* x    = (const float*)d_in[0];
    const float* cs   = (const float*)d_in[1];
    const float* sn   = (const float*)d_in[2];
    const float* qw   = (const float*)d_in[3];
    const float* kvw  = (const float*)d_in[4];
    const float* lnw  = (const float*)d_in[5];
    const float* wukt = (const float*)d_in[6];
    const float* wuv  = (const float*)d_in[7];
    const float* ow   = (const float*)d_in[8];
    float* out        = (float*)d_out;

    float *pq, *pckv, *pkf, *pqf, *psc, *pol, *py;
    cudaGetSymbolAddress((void**)&pq,   g_q);
    cudaGetSymbolAddress((void**)&pckv, g_ckv);
    cudaGetSymbolAddress((void**)&pkf,  g_kfull);
    cudaGetSymbolAddress((void**)&pqf,  g_qfull);
    cudaGetSymbolAddress((void**)&psc,  g_scores);
    cudaGetSymbolAddress((void**)&pol,  g_outlat);
    cudaGetSymbolAddress((void**)&py,   g_y);

    const float scale = 1.0f / sqrtf((float)(DN + DR));

    // 1) q = x @ q_proj_w^T         [4096,3072]
    gemm_tc<true, 0><<<dim3(24, 32, 1), 256>>>(
        x, qw, pq, TT, HH * DQ, HID, HID, HID, HH * DQ, 1.f,
        0, 0, 0, 0, 0, 0, 1);

    // 2) ckv = x @ kv_a_proj_w^T    [4096,576]
    gemm_tc<true, 0><<<dim3(5, 32, 1), 256>>>(
        x, kvw, pckv, TT, DK, HID, HID, HID, DK, 1.f,
        0, 0, 0, 0, 0, 0, 1);

    // 3) k_full = [rmsnorm(kv_c)*w | rope(k_rot)]
    kv_transform_kernel<<<TT, 256>>>(pckv, cs, sn, lnw, pkf);

    // 4) q_full[...,512:576] = rope(q_rot)
    q_rope_kernel<<<TT, 256>>>(pq, cs, sn, pqf);

    // 5) q_full[...,0:512] = q_pass @ W_UK_T[h]   (batched over h)
    gemm_tc<false, 0><<<dim3(4, 32, HH), 256>>>(
        pq, wukt, pqf, TT, LL, DN, HH * DQ, LL, HH * DK, 1.f,
        0, DQ, 0, (long)DN * LL, 0, DK, HH);

    // 6) scores = scale * q_full @ k_full^T   (batched over b,h; upper blocks skipped)
    gemm_tc<true, 1><<<dim3(16, 16, BB * HH), 256>>>(
        pqf, pkf, psc, SS, SS, DK, HH * DK, DK, SS, scale,
        (long)SS * HH * DK, DK,
        (long)SS * DK, 0,
        (long)HH * SS * SS, (long)SS * SS, HH);

    // 7) causal softmax in place
    softmax_kernel<<<dim3(SS, BB * HH), 256>>>(psc);

    // 8) out_lat = attn @ kv_c   (K loop clamped by causality)
    gemm_tc<false, 2><<<dim3(4, 16, BB * HH), 256>>>(
        psc, pkf, pol, SS, LL, SS, SS, DK, HH * LL, 1.f,
        (long)HH * SS * SS, (long)SS * SS,
        (long)SS * DK, 0,
        (long)SS * HH * LL, LL, HH);

    // 9) y[:, h*128:(h+1)*128] = out_lat[:,h,:] @ W_UV[h]
    gemm_tc<false, 0><<<dim3(1, 32, HH), 256>>>(
        pol, wuv, py, TT, DV, LL, HH * LL, DV, HH * DV, 1.f,
        0, LL, 0, (long)LL * DV, 0, DV, HH);

    // 10) out = y @ o_proj_w^T
    gemm_tc<true, 0><<<dim3(16, 32, 1), 256>>>(
        py, ow, out, TT, HID, HH * DV, HH * DV, HH * DV, HID, 1.f,
        0, 0, 0, 0, 0, 0, 1);
}

// round 4
// speedup vs baseline: 2.5067x; 1.0600x over previous
#include <cuda_runtime.h>
#include <cuda_bf16.h>
#include <math.h>
#include <stdint.h>

// ---------------- problem constants ----------------
#define BB   2
#define SS   2048
#define TT   4096          // B*S
#define HID  2048
#define HH   16
#define DN   128
#define DR   64
#define DV   128
#define LL   512
#define DQ   (DN + DR)     // 192
#define DK   (LL + DR)     // 576

// ---------------- scratch (static device memory; no allocations) ----------------
__device__ float g_q     [(long)TT * HH * DQ];
__device__ float g_ckv   [(long)TT * DK];
__device__ float g_kfull [(long)TT * DK];
__device__ float g_qfull [(long)TT * HH * DK];
__device__ float g_scores[(long)BB * HH * SS * SS];
__device__ float g_outlat[(long)TT * HH * LL];
__device__ float g_y     [(long)TT * HH * DV];

// ---------------- tf32 helpers ----------------
__device__ __forceinline__ float f2tf(float x) {
    uint32_t u;
    asm("cvt.rna.tf32.f32 %0, %1;" : "=r"(u) : "f"(x));
    return __uint_as_float(u);
}

__device__ __forceinline__ void mma_tf32(float c[4], const float a[4], const float b[2]) {
    asm volatile(
        "mma.sync.aligned.m16n8k8.row.col.f32.tf32.tf32.f32 "
        "{%0,%1,%2,%3}, {%4,%5,%6,%7}, {%8,%9}, {%0,%1,%2,%3};"
        : "+f"(c[0]), "+f"(c[1]), "+f"(c[2]), "+f"(c[3])
        : "r"(__float_as_uint(a[0])), "r"(__float_as_uint(a[1])),
          "r"(__float_as_uint(a[2])), "r"(__float_as_uint(a[3])),
          "r"(__float_as_uint(b[0])), "r"(__float_as_uint(b[1])));
}

// ---------------- tensor-core TF32 GEMM (double-buffered) ----------------
// C[M,N] = alpha * A @ op(B)
//   BT=true : B is [N,K] row-major (C = A @ B^T)
//   BT=false: B is [K,N] row-major (C = A @ B)
// CAUSAL=1 : skip blocks strictly above the diagonal (scores)
// CAUSAL=2 : clamp K loop to row0+BM (attn rows zero beyond diagonal)
// Batched over grid.z: z = b*nH + h with per-matrix element offsets.
// Requirements: M % 128 == 0, K % 16 == 0, rows 16B-aligned.
constexpr int BM = 128, BN = 128, BK = 16;
constexpr int SKP = BK + 4;   // smem row stride (floats)

template<bool BT, int CAUSAL>
__global__ __launch_bounds__(256, 2)
void gemm_tc(const float* __restrict__ A, const float* __restrict__ Bm,
             float* __restrict__ C,
             int M, int N, int K, int lda, int ldb, int ldc, float alpha,
             long aB, long aH, long bB, long bH, long cB, long cH, int nH)
{
    int z  = blockIdx.z;
    int bb = z / nH, hh = z - bb * nH;
    A  += (long)bb * aB + (long)hh * aH;
    Bm += (long)bb * bB + (long)hh * bH;
    C  += (long)bb * cB + (long)hh * cH;

    const int row0 = blockIdx.y * BM;
    const int col0 = blockIdx.x * BN;
    if (CAUSAL == 1 && col0 > row0 + BM - 1) return;
    int Keff = K;
    if (CAUSAL == 2) { int lim = row0 + BM; Keff = lim < K ? lim : K; }

    __shared__ float As[2][BM][SKP];   // [buf][m][k]
    __shared__ float Bs[2][BN][SKP];   // [buf][n][k]

    const int tid  = threadIdx.x;
    const int lane = tid & 31;
    const int warp = tid >> 5;
    const int wm   = warp & 3;      // 4 warps along M
    const int wn   = warp >> 2;     // 2 warps along N
    const int gid  = lane >> 2;     // 0..7
    const int tig  = lane & 3;      // 0..3

    float acc[2][8][4];
    #pragma unroll
    for (int i = 0; i < 2; i++)
        #pragma unroll
        for (int j = 0; j < 8; j++)
            #pragma unroll
            for (int r = 0; r < 4; r++) acc[i][j][r] = 0.f;

    // global-load assignments
    const int arow = tid >> 1;            // 0..127
    const int acol = (tid & 1) << 3;      // 0 or 8
    const int nbk  = tid >> 4;            // 0..15 (NN: k row)
    const int nbc  = tid & 15;            // NN: col lane

    float4 pa0, pa1, pb0, pb1;            // prefetch regs (BT path)
    float  pbn[8];                        // prefetch regs (NN path)

    auto load_tile = [&](int k0) {
        pa0 = *reinterpret_cast<const float4*>(A + (long)(row0 + arow) * lda + k0 + acol);
        pa1 = *reinterpret_cast<const float4*>(A + (long)(row0 + arow) * lda + k0 + acol + 4);
        if (BT) {
            int bc = col0 + arow;
            if (bc < N) {
                pb0 = *reinterpret_cast<const float4*>(Bm + (long)bc * ldb + k0 + acol);
                pb1 = *reinterpret_cast<const float4*>(Bm + (long)bc * ldb + k0 + acol + 4);
            } else {
                pb0 = make_float4(0.f,0.f,0.f,0.f);
                pb1 = make_float4(0.f,0.f,0.f,0.f);
            }
        } else {
            const float* brow = Bm + (long)(k0 + nbk) * ldb + col0;
            #pragma unroll
            for (int i = 0; i < 8; i++) {
                int c = nbc + 16 * i;
                pbn[i] = (col0 + c < N) ? brow[c] : 0.f;
            }
        }
    };

    auto store_tile = [&](int buf) {
        As[buf][arow][acol + 0] = f2tf(pa0.x); As[buf][arow][acol + 1] = f2tf(pa0.y);
        As[buf][arow][acol + 2] = f2tf(pa0.z); As[buf][arow][acol + 3] = f2tf(pa0.w);
        As[buf][arow][acol + 4] = f2tf(pa1.x); As[buf][arow][acol + 5] = f2tf(pa1.y);
        As[buf][arow][acol + 6] = f2tf(pa1.z); As[buf][arow][acol + 7] = f2tf(pa1.w);
        if (BT) {
            Bs[buf][arow][acol + 0] = f2tf(pb0.x); Bs[buf][arow][acol + 1] = f2tf(pb0.y);
            Bs[buf][arow][acol + 2] = f2tf(pb0.z); Bs[buf][arow][acol + 3] = f2tf(pb0.w);
            Bs[buf][arow][acol + 4] = f2tf(pb1.x); Bs[buf][arow][acol + 5] = f2tf(pb1.y);
            Bs[buf][arow][acol + 6] = f2tf(pb1.z); Bs[buf][arow][acol + 7] = f2tf(pb1.w);
        } else {
            #pragma unroll
            for (int i = 0; i < 8; i++)
                Bs[buf][nbc + 16 * i][nbk] = f2tf(pbn[i]);
        }
    };

    const int nT = Keff / BK;
    load_tile(0);
    store_tile(0);
    __syncthreads();

    for (int it = 0; it < nT; it++) {
        const int cur = it & 1;
        if (it + 1 < nT) load_tile((it + 1) * BK);   // LDG overlaps compute below

        #pragma unroll
        for (int kk = 0; kk < BK; kk += 8) {
            float a[2][4];
            #pragma unroll
            for (int mi = 0; mi < 2; mi++) {
                int mr = wm * 32 + mi * 16 + gid;
                a[mi][0] = As[cur][mr    ][kk + tig    ];
                a[mi][1] = As[cur][mr + 8][kk + tig    ];
                a[mi][2] = As[cur][mr    ][kk + tig + 4];
                a[mi][3] = As[cur][mr + 8][kk + tig + 4];
            }
            float b[8][2];
            #pragma unroll
            for (int ni = 0; ni < 8; ni++) {
                int nc = wn * 64 + ni * 8 + gid;
                b[ni][0] = Bs[cur][nc][kk + tig    ];
                b[ni][1] = Bs[cur][nc][kk + tig + 4];
            }
            #pragma unroll
            for (int mi = 0; mi < 2; mi++)
                #pragma unroll
                for (int ni = 0; ni < 8; ni++)
                    mma_tf32(acc[mi][ni], a[mi], b[ni]);
        }

        if (it + 1 < nT) store_tile(cur ^ 1);        // stalls on LDG, hidden by mma above
        __syncthreads();
    }

    // epilogue
    #pragma unroll
    for (int mi = 0; mi < 2; mi++) {
        int r0 = row0 + wm * 32 + mi * 16 + gid;
        #pragma unroll
        for (int ni = 0; ni < 8; ni++) {
            int c = col0 + wn * 64 + ni * 8 + 2 * tig;
            if (c < N) {
                float2 v0 = make_float2(alpha * acc[mi][ni][0], alpha * acc[mi][ni][1]);
                float2 v1 = make_float2(alpha * acc[mi][ni][2], alpha * acc[mi][ni][3]);
                *reinterpret_cast<float2*>(C + (long)r0 * ldc + c)       = v0;
                *reinterpret_cast<float2*>(C + (long)(r0 + 8) * ldc + c) = v1;
            }
        }
    }
}

// ---------------- kv: RMSNorm + RoPE(k) -> k_full [T,576] ----------------
__global__ __launch_bounds__(256)
void kv_transform_kernel(const float* __restrict__ ckv,
                         const float* __restrict__ cs, const float* __restrict__ sn,
                         const float* __restrict__ lnw, float* __restrict__ kfull)
{
    const int t = blockIdx.x;
    const float* row = ckv + (long)t * DK;
    const int tid = threadIdx.x;

    float x0 = row[tid], x1 = row[tid + 256];
    float ss = x0 * x0 + x1 * x1;
    #pragma unroll
    for (int o = 16; o; o >>= 1) ss += __shfl_xor_sync(0xffffffffu, ss, o);
    __shared__ float red[8];
    if ((tid & 31) == 0) red[tid >> 5] = ss;
    __syncthreads();
    float tot = 0.f;
    #pragma unroll
    for (int w = 0; w < 8; w++) tot += red[w];
    float inv = rsqrtf(tot / (float)LL + 1e-6f);

    float* out = kfull + (long)t * DK;
    out[tid]       = x0 * inv * lnw[tid];
    out[tid + 256] = x1 * inv * lnw[tid + 256];

    if (tid < DR) {
        int j = tid;
        float c = cs[(long)t * DR + j], s = sn[(long)t * DR + j];
        const float* r = row + LL;
        float val;
        if (j < 32) val = r[2 * j] * c - r[2 * j + 1] * s;
        else { int m = j - 32; val = r[2 * m + 1] * c + r[2 * m] * s; }
        out[LL + j] = val;
    }
}

// ---------------- q RoPE -> q_full[..., 512:576] ----------------
__global__ __launch_bounds__(256)
void q_rope_kernel(const float* __restrict__ q,
                   const float* __restrict__ cs, const float* __restrict__ sn,
                   float* __restrict__ qfull)
{
    const int t = blockIdx.x;
    const int tid = threadIdx.x;
    #pragma unroll
    for (int l = 0; l < 4; l++) {
        int idx = tid + l * 256;          // 0..1023 = h*64 + j
        int h = idx >> 6, j = idx & 63;
        const float* r = q + ((long)t * HH + h) * DQ + DN;
        float c = cs[(long)t * DR + j], s = sn[(long)t * DR + j];
        float val;
        if (j < 32) val = r[2 * j] * c - r[2 * j + 1] * s;
        else { int m = j - 32; val = r[2 * m + 1] * c + r[2 * m] * s; }
        qfull[((long)t * HH + h) * DK + LL + j] = val;
    }
}

// ---------------- causal softmax (in place), zero-fills t > s ----------------
__global__ __launch_bounds__(256)
void softmax_kernel(float* __restrict__ P)
{
    const int s = blockIdx.x;
    long base = ((long)blockIdx.y * SS + s) * (long)SS;
    const int valid = s + 1;
    const int tid = threadIdx.x;

    float v[8];
    float mx = -1e30f;
    #pragma unroll
    for (int l = 0; l < 8; l++) {
        int idx = tid + l * 256;
        v[l] = (idx < valid) ? P[base + idx] : -1e30f;
        mx = fmaxf(mx, v[l]);
    }
    __shared__ float red[8];
    #pragma unroll
    for (int o = 16; o; o >>= 1) mx = fmaxf(mx, __shfl_xor_sync(0xffffffffu, mx, o));
    if ((tid & 31) == 0) red[tid >> 5] = mx;
    __syncthreads();
    float m = red[0];
    #pragma unroll
    for (int w = 1; w < 8; w++) m = fmaxf(m, red[w]);
    __syncthreads();

    float sum = 0.f;
    #pragma unroll
    for (int l = 0; l < 8; l++) {
        int idx = tid + l * 256;
        v[l] = (idx < valid) ? __expf(v[l] - m) : 0.f;
        sum += v[l];
    }
    #pragma unroll
    for (int o = 16; o; o >>= 1) sum += __shfl_xor_sync(0xffffffffu, sum, o);
    if ((tid & 31) == 0) red[tid >> 5] = sum;
    __syncthreads();
    float tot = 0.f;
    #pragma unroll
    for (int w = 0; w < 8; w++) tot += red[w];
    float invs = 1.f / tot;

    #pragma unroll
    for (int l = 0; l < 8; l++) {
        int idx = tid + l * 256;
        P[base + idx] = v[l] * invs;
    }
}

// ---------------- launch ----------------
extern "C" void kernel_launch(void* const* d_in, const int* in_sizes, int n_in,
                              void* d_out, int out_size)
{
    const float* x    = (const float*)d_in[0];
    const float* cs   = (const float*)d_in[1];
    const float* sn   = (const float*)d_in[2];
    const float* qw   = (const float*)d_in[3];
    const float* kvw  = (const float*)d_in[4];
    const float* lnw  = (const float*)d_in[5];
    const float* wukt = (const float*)d_in[6];
    const float* wuv  = (const float*)d_in[7];
    const float* ow   = (const float*)d_in[8];
    float* out        = (float*)d_out;

    float *pq, *pckv, *pkf, *pqf, *psc, *pol, *py;
    cudaGetSymbolAddress((void**)&pq,   g_q);
    cudaGetSymbolAddress((void**)&pckv, g_ckv);
    cudaGetSymbolAddress((void**)&pkf,  g_kfull);
    cudaGetSymbolAddress((void**)&pqf,  g_qfull);
    cudaGetSymbolAddress((void**)&psc,  g_scores);
    cudaGetSymbolAddress((void**)&pol,  g_outlat);
    cudaGetSymbolAddress((void**)&py,   g_y);

    const float scale = 1.0f / sqrtf((float)(DN + DR));

    // 1) q = x @ q_proj_w^T         [4096,3072]
    gemm_tc<true, 0><<<dim3(24, 32, 1), 256>>>(
        x, qw, pq, TT, HH * DQ, HID, HID, HID, HH * DQ, 1.f,
        0, 0, 0, 0, 0, 0, 1);

    // 2) ckv = x @ kv_a_proj_w^T    [4096,576]
    gemm_tc<true, 0><<<dim3(5, 32, 1), 256>>>(
        x, kvw, pckv, TT, DK, HID, HID, HID, DK, 1.f,
        0, 0, 0, 0, 0, 0, 1);

    // 3) k_full = [rmsnorm(kv_c)*w | rope(k_rot)]
    kv_transform_kernel<<<TT, 256>>>(pckv, cs, sn, lnw, pkf);

    // 4) q_full[...,512:576] = rope(q_rot)
    q_rope_kernel<<<TT, 256>>>(pq, cs, sn, pqf);

    // 5) q_full[...,0:512] = q_pass @ W_UK_T[h]   (batched over h)
    gemm_tc<false, 0><<<dim3(4, 32, HH), 256>>>(
        pq, wukt, pqf, TT, LL, DN, HH * DQ, LL, HH * DK, 1.f,
        0, DQ, 0, (long)DN * LL, 0, DK, HH);

    // 6) scores = scale * q_full @ k_full^T   (batched over b,h; upper blocks skipped)
    gemm_tc<true, 1><<<dim3(16, 16, BB * HH), 256>>>(
        pqf, pkf, psc, SS, SS, DK, HH * DK, DK, SS, scale,
        (long)SS * HH * DK, DK,
        (long)SS * DK, 0,
        (long)HH * SS * SS, (long)SS * SS, HH);

    // 7) causal softmax in place
    softmax_kernel<<<dim3(SS, BB * HH), 256>>>(psc);

    // 8) out_lat = attn @ kv_c   (K loop clamped by causality)
    gemm_tc<false, 2><<<dim3(4, 16, BB * HH), 256>>>(
        psc, pkf, pol, SS, LL, SS, SS, DK, HH * LL, 1.f,
        (long)HH * SS * SS, (long)SS * SS,
        (long)SS * DK, 0,
        (long)SS * HH * LL, LL, HH);

    // 9) y[:, h*128:(h+1)*128] = out_lat[:,h,:] @ W_UV[h]
    gemm_tc<false, 0><<<dim3(1, 32, HH), 256>>>(
        pol, wuv, py, TT, DV, LL, HH * LL, DV, HH * DV, 1.f,
        0, LL, 0, (long)LL * DV, 0, DV, HH);

    // 10) out = y @ o_proj_w^T
    gemm_tc<true, 0><<<dim3(16, 32, 1), 256>>>(
        py, ow, out, TT, HID, HH * DV, HH * DV, HH * DV, HID, 1.f,
        0, 0, 0, 0, 0, 0, 1);
}